// round 1
// baseline (speedup 1.0000x reference)
#include <cuda_runtime.h>
#include <cstdint>
#include <cstddef>

#define DM 512      // D_INNER / D_MODEL
#define NS 128      // N_STATE
#define RK 32       // DT_RANK
#define XDW 288     // DT_RANK + 2*N_STATE

// ---------------------------------------------------------------------------
// Static scratch pool (no cudaMalloc allowed)
// ---------------------------------------------------------------------------
__device__ float g_pool[33000000];

// offsets (floats)
static const size_t OFF_F     = 0;                      // 2048*512
static const size_t OFF_XZ_F  = 1048576;                // 2048*1024
static const size_t OFF_XZ_R  = 3145728;
static const size_t OFF_XS_F  = 5242880;                // 2048*512
static const size_t OFF_XS_R  = 6291456;
static const size_t OFF_XD_F  = 7340032;                // 2048*288
static const size_t OFF_XD_R  = 7929856;
static const size_t OFF_DT_F  = 8519680;                // 2048*512
static const size_t OFF_DT_R  = 9568256;
static const size_t OFF_Y_F   = 10616832;               // 2048*512
static const size_t OFF_Y_R   = 11665408;
static const size_t OFF_YP_F  = 12713984;               // 2048*512
static const size_t OFF_YP_R  = 13762560;
static const size_t OFF_YM_F  = 14811136;               // 2048*512 (softmaxed in place)
static const size_t OFF_YM_R  = 15859712;
static const size_t OFF_SFI   = 16908288;               // 2049*1024
static const size_t OFF_SIF   = 19006464;
static const size_t OFF_XZ_CF = 21104640;               // 2049*1024
static const size_t OFF_XZ_CR = 23202816;
static const size_t OFF_XS_CF = 25300992;               // 2049*512
static const size_t OFF_XS_CR = 26350080;
static const size_t OFF_XD_CF = 27399168;               // 2049*288
static const size_t OFF_XD_CR = 27989280;
static const size_t OFF_DT_CF = 28579392;               // 2049*512
static const size_t OFF_DT_CR = 29628480;
static const size_t OFF_Y_CF  = 30677568;               // 2049*512
static const size_t OFF_Y_CR  = 31726656;
static const size_t OFF_V     = 32775744;               // 1024 (dir*512+d)
static const size_t OFF_O     = 32776768;               // 1024 (of, oi)

// ---------------------------------------------------------------------------
// GEMM: C[M,N] = act( A[M,K] @ B[K,N] + bias )
// 128x128 block tile, BK=8, 256 threads, 8x8 microtile. arev reverses A rows.
// act: 0 none, 1 relu, 2 softplus
// ---------------------------------------------------------------------------
__global__ void gemm_kernel(const float* __restrict__ A, const float* __restrict__ B,
                            const float* __restrict__ bias, float* __restrict__ C,
                            int M, int N, int K, int lda, int ldb, int ldc,
                            int arev, int act)
{
    __shared__ float As[8][128];
    __shared__ float Bs[8][128];
    const int tid = threadIdx.x;
    const int bm = blockIdx.y * 128;
    const int bn = blockIdx.x * 128;
    const int tr = (tid >> 4) * 8;
    const int tc = (tid & 15) * 8;

    float acc[8][8];
#pragma unroll
    for (int i = 0; i < 8; i++)
#pragma unroll
        for (int j = 0; j < 8; j++) acc[i][j] = 0.f;

    const int arow = tid >> 1;
    const int acol = (tid & 1) * 4;
    const int brow = tid >> 5;
    const int bcol = (tid & 31) * 4;

    for (int k0 = 0; k0 < K; k0 += 8) {
        float4 va = make_float4(0.f, 0.f, 0.f, 0.f);
        int m = bm + arow;
        if (m < M) {
            int mm = arev ? (M - 1 - m) : m;
            va = *reinterpret_cast<const float4*>(A + (size_t)mm * lda + k0 + acol);
        }
        As[acol + 0][arow] = va.x;
        As[acol + 1][arow] = va.y;
        As[acol + 2][arow] = va.z;
        As[acol + 3][arow] = va.w;

        float4 vb = make_float4(0.f, 0.f, 0.f, 0.f);
        int n = bn + bcol;
        const float* Brow = B + (size_t)(k0 + brow) * ldb;
        if (n + 3 < N) {
            vb = *reinterpret_cast<const float4*>(Brow + n);
        } else if (n < N) {
            vb.x = Brow[n];
            if (n + 1 < N) vb.y = Brow[n + 1];
            if (n + 2 < N) vb.z = Brow[n + 2];
        }
        *reinterpret_cast<float4*>(&Bs[brow][bcol]) = vb;

        __syncthreads();
#pragma unroll
        for (int kk = 0; kk < 8; kk++) {
            float a[8], b[8];
            *reinterpret_cast<float4*>(&a[0]) = *reinterpret_cast<const float4*>(&As[kk][tr]);
            *reinterpret_cast<float4*>(&a[4]) = *reinterpret_cast<const float4*>(&As[kk][tr + 4]);
            *reinterpret_cast<float4*>(&b[0]) = *reinterpret_cast<const float4*>(&Bs[kk][tc]);
            *reinterpret_cast<float4*>(&b[4]) = *reinterpret_cast<const float4*>(&Bs[kk][tc + 4]);
#pragma unroll
            for (int i = 0; i < 8; i++)
#pragma unroll
                for (int j = 0; j < 8; j++) acc[i][j] = fmaf(a[i], b[j], acc[i][j]);
        }
        __syncthreads();
    }

#pragma unroll
    for (int i = 0; i < 8; i++) {
        int m = bm + tr + i;
        if (m >= M) continue;
#pragma unroll
        for (int j = 0; j < 8; j++) {
            int n = bn + tc + j;
            if (n >= N) continue;
            float v = acc[i][j];
            if (bias) v += bias[n];
            if (act == 1) v = v > 0.f ? v : 0.f;
            else if (act == 2) v = (v > 20.f) ? v : log1pf(__expf(v));
            C[(size_t)m * ldc + n] = v;
        }
    }
}

// ---------------------------------------------------------------------------
// Causal depthwise conv1d (K=4) + SiLU. xz rows are 1024 wide; x = cols [0,512)
// ---------------------------------------------------------------------------
__global__ void conv_silu_kernel(const float* __restrict__ xz, const float* __restrict__ w,
                                 const float* __restrict__ b, float* __restrict__ xs, int T)
{
    int idx = blockIdx.x * blockDim.x + threadIdx.x;
    if (idx >= T * DM) return;
    int t = idx >> 9;
    int d = idx & 511;
    float acc = b[d];
#pragma unroll
    for (int k = 0; k < 4; k++) {
        int tt = t + k - 3;
        if (tt >= 0) acc = fmaf(xz[(size_t)tt * 1024 + d], w[d * 4 + k], acc);
    }
    xs[idx] = acc / (1.f + __expf(-acc));
}

// ---------------------------------------------------------------------------
// Selective scan. One warp per channel d; lane holds 4 of the 128 states.
// blockIdx.y selects direction (two independent scans per launch).
// xd layout: row stride 288; dt-lowrank [0,32), B [32,160), C [160,288)
// ---------------------------------------------------------------------------
__global__ void scan_kernel(const float* __restrict__ dt0, const float* __restrict__ xs0,
                            const float* __restrict__ xd0, float* __restrict__ y0,
                            const float* __restrict__ dt1, const float* __restrict__ xs1,
                            const float* __restrict__ xd1, float* __restrict__ y1,
                            const float* __restrict__ A_log, int T)
{
    const float* dt = blockIdx.y ? dt1 : dt0;
    const float* xs = blockIdx.y ? xs1 : xs0;
    const float* xd = blockIdx.y ? xd1 : xd0;
    float* y = blockIdx.y ? y1 : y0;

    int warp = threadIdx.x >> 5;
    int lane = threadIdx.x & 31;
    int d = blockIdx.x * 8 + warp;

    float4 alv = *reinterpret_cast<const float4*>(A_log + (size_t)d * NS + lane * 4);
    float a0 = -expf(alv.x), a1 = -expf(alv.y), a2 = -expf(alv.z), a3 = -expf(alv.w);
    float h0 = 0.f, h1 = 0.f, h2 = 0.f, h3 = 0.f;
    const float* pb = xd + RK + lane * 4;
    const float* pc = xd + RK + NS + lane * 4;

    for (int t = 0; t < T; t++) {
        float dtv = dt[(size_t)t * DM + d];
        float xv  = xs[(size_t)t * DM + d];
        float dtx = dtv * xv;
        float4 Bv = *reinterpret_cast<const float4*>(pb + (size_t)t * XDW);
        float4 Cv = *reinterpret_cast<const float4*>(pc + (size_t)t * XDW);
        h0 = fmaf(h0, __expf(dtv * a0), dtx * Bv.x);
        h1 = fmaf(h1, __expf(dtv * a1), dtx * Bv.y);
        h2 = fmaf(h2, __expf(dtv * a2), dtx * Bv.z);
        h3 = fmaf(h3, __expf(dtv * a3), dtx * Bv.w);
        float acc = h0 * Cv.x + h1 * Cv.y + h2 * Cv.z + h3 * Cv.w;
        acc += __shfl_xor_sync(0xffffffffu, acc, 16);
        acc += __shfl_xor_sync(0xffffffffu, acc, 8);
        acc += __shfl_xor_sync(0xffffffffu, acc, 4);
        acc += __shfl_xor_sync(0xffffffffu, acc, 2);
        acc += __shfl_xor_sync(0xffffffffu, acc, 1);
        if (lane == 0) y[(size_t)t * DM + d] = acc;
    }
}

// ---------------------------------------------------------------------------
// y = (scan_y + xs*Dp) * silu(z), z = xz[:, 512:1024]
// ---------------------------------------------------------------------------
__global__ void epi_kernel(const float* __restrict__ y, const float* __restrict__ xs,
                           const float* __restrict__ xz, const float* __restrict__ Dp,
                           float* __restrict__ out, int T)
{
    int idx = blockIdx.x * blockDim.x + threadIdx.x;
    if (idx >= T * DM) return;
    int t = idx >> 9, d = idx & 511;
    float v = fmaf(xs[idx], Dp[d], y[idx]);
    float z = xz[(size_t)t * 1024 + 512 + d];
    out[idx] = v * (z / (1.f + __expf(-z)));
}

// ---------------------------------------------------------------------------
// Row-wise softmax over 512 columns, in place. 128 threads per row.
// ---------------------------------------------------------------------------
__global__ void softmax512_kernel(float* __restrict__ data)
{
    int row = blockIdx.x;
    float* p = data + (size_t)row * DM;
    int tid = threadIdx.x;
    float v[4];
    float mx = -1e30f;
#pragma unroll
    for (int j = 0; j < 4; j++) { v[j] = p[tid + 128 * j]; mx = fmaxf(mx, v[j]); }
#pragma unroll
    for (int o = 16; o; o >>= 1) mx = fmaxf(mx, __shfl_xor_sync(0xffffffffu, mx, o));
    __shared__ float red[4];
    if ((tid & 31) == 0) red[tid >> 5] = mx;
    __syncthreads();
    mx = fmaxf(fmaxf(red[0], red[1]), fmaxf(red[2], red[3]));
    float s = 0.f;
#pragma unroll
    for (int j = 0; j < 4; j++) { v[j] = __expf(v[j] - mx); s += v[j]; }
#pragma unroll
    for (int o = 16; o; o >>= 1) s += __shfl_xor_sync(0xffffffffu, s, o);
    __shared__ float red2[4];
    if ((tid & 31) == 0) red2[tid >> 5] = s;
    __syncthreads();
    s = red2[0] + red2[1] + red2[2] + red2[3];
    float inv = 1.f / s;
#pragma unroll
    for (int j = 0; j < 4; j++) p[tid + 128 * j] = v[j] * inv;
}

// ---------------------------------------------------------------------------
// Build cross-scan sequences: seq_fi[t] = [yf[t], yi[t]], seq_if[t] = [yi[t], yf[t]],
// yi[t] = yrev[2047-t]; last row = cls token.
// ---------------------------------------------------------------------------
__global__ void build_seq_kernel(const float* __restrict__ yf, const float* __restrict__ yr,
                                 const float* __restrict__ cls1, const float* __restrict__ cls2,
                                 float* __restrict__ sfi, float* __restrict__ sif)
{
    int idx = blockIdx.x * blockDim.x + threadIdx.x;
    if (idx >= 2049 * 1024) return;
    int t = idx >> 10, j = idx & 1023;
    float vfi, vif;
    if (t < 2048) {
        float yi = (j < 512) ? yr[(size_t)(2047 - t) * DM + j] : yr[(size_t)(2047 - t) * DM + (j - 512)];
        float yfv = (j < 512) ? yf[(size_t)t * DM + j] : yf[(size_t)t * DM + (j - 512)];
        vfi = (j < 512) ? yfv : yi;
        vif = (j < 512) ? yi : yfv;
    } else {
        vfi = cls1[j];
        vif = cls2[j];
    }
    sfi[idx] = vfi;
    sif[idx] = vif;
}

// ---------------------------------------------------------------------------
// Cross-mamba last-row epilogue: v[d] = (y + xs*Dp) * silu(z) at t = T-1
// ---------------------------------------------------------------------------
__global__ void lastrow_epi_kernel(const float* __restrict__ y0, const float* __restrict__ xs0,
                                   const float* __restrict__ xz0,
                                   const float* __restrict__ y1, const float* __restrict__ xs1,
                                   const float* __restrict__ xz1,
                                   const float* __restrict__ Dp, float* __restrict__ v, int T)
{
    int dir = blockIdx.x;
    const float* y  = dir ? y1 : y0;
    const float* xs = dir ? xs1 : xs0;
    const float* xz = dir ? xz1 : xz0;
    int d = threadIdx.x;
    size_t r = (size_t)(T - 1);
    float val = fmaf(xs[r * DM + d], Dp[d], y[r * DM + d]);
    float z = xz[r * 1024 + 512 + d];
    v[dir * DM + d] = val * (z / (1.f + __expf(-z)));
}

// ---------------------------------------------------------------------------
// o[dir] = v[dir] @ out_w  (512x512 matvec)
// ---------------------------------------------------------------------------
__global__ void matvec_outw_kernel(const float* __restrict__ v, const float* __restrict__ W,
                                   float* __restrict__ o)
{
    int dir = blockIdx.y;
    int j = blockIdx.x * 256 + threadIdx.x;
    __shared__ float sv[DM];
    for (int i = threadIdx.x; i < DM; i += 256) sv[i] = v[dir * DM + i];
    __syncthreads();
    float s = 0.f;
    for (int dd = 0; dd < DM; dd++) s = fmaf(sv[dd], W[(size_t)dd * DM + j], s);
    o[dir * DM + j] = s;
}

// ---------------------------------------------------------------------------
// out = concat(of, oi) @ cls_w + cls_b  -> [1,2]
// ---------------------------------------------------------------------------
__global__ void final_kernel(const float* __restrict__ o, const float* __restrict__ cls_w,
                             const float* __restrict__ cls_b, float* __restrict__ out)
{
    int tid = threadIdx.x; // 256
    float s0 = 0.f, s1 = 0.f;
    for (int j = tid; j < 512; j += 256) {
        float a = o[j], b = o[512 + j];
        s0 += a * cls_w[j * 2 + 0] + b * cls_w[(512 + j) * 2 + 0];
        s1 += a * cls_w[j * 2 + 1] + b * cls_w[(512 + j) * 2 + 1];
    }
#pragma unroll
    for (int off = 16; off; off >>= 1) {
        s0 += __shfl_xor_sync(0xffffffffu, s0, off);
        s1 += __shfl_xor_sync(0xffffffffu, s1, off);
    }
    __shared__ float r0[8], r1[8];
    if ((tid & 31) == 0) { r0[tid >> 5] = s0; r1[tid >> 5] = s1; }
    __syncthreads();
    if (tid == 0) {
        float t0 = 0.f, t1 = 0.f;
        for (int w = 0; w < 8; w++) { t0 += r0[w]; t1 += r1[w]; }
        out[0] = t0 + cls_b[0];
        out[1] = t1 + cls_b[1];
    }
}

// ---------------------------------------------------------------------------
// Host orchestration
// ---------------------------------------------------------------------------
extern "C" void kernel_launch(void* const* d_in, const int* in_sizes, int n_in,
                              void* d_out, int out_size)
{
    const float* x        = (const float*)d_in[0];
    const float* feat_w   = (const float*)d_in[1];
    const float* feat_b   = (const float*)d_in[2];
    const float* cls1     = (const float*)d_in[3];
    const float* cls2     = (const float*)d_in[4];
    const float* cls_w    = (const float*)d_in[5];
    const float* cls_b    = (const float*)d_in[6];
    const float* m_in_w   = (const float*)d_in[7];
    const float* m_conv_w = (const float*)d_in[8];
    const float* m_conv_b = (const float*)d_in[9];
    const float* m_xproj  = (const float*)d_in[10];
    const float* m_dt_w   = (const float*)d_in[11];
    const float* m_dt_b   = (const float*)d_in[12];
    const float* m_A_log  = (const float*)d_in[13];
    const float* m_D      = (const float*)d_in[14];
    const float* m_out_w  = (const float*)d_in[15];
    const float* c_in_w   = (const float*)d_in[16];
    const float* c_conv_w = (const float*)d_in[17];
    const float* c_conv_b = (const float*)d_in[18];
    const float* c_xproj  = (const float*)d_in[19];
    const float* c_dt_w   = (const float*)d_in[20];
    const float* c_dt_b   = (const float*)d_in[21];
    const float* c_A_log  = (const float*)d_in[22];
    const float* c_D      = (const float*)d_in[23];
    const float* c_out_w  = (const float*)d_in[24];

    float* pool = nullptr;
    cudaGetSymbolAddress((void**)&pool, g_pool);

    float* f     = pool + OFF_F;
    float* xz_f  = pool + OFF_XZ_F;
    float* xz_r  = pool + OFF_XZ_R;
    float* xs_f  = pool + OFF_XS_F;
    float* xs_r  = pool + OFF_XS_R;
    float* xd_f  = pool + OFF_XD_F;
    float* xd_r  = pool + OFF_XD_R;
    float* dt_f  = pool + OFF_DT_F;
    float* dt_r  = pool + OFF_DT_R;
    float* y_f   = pool + OFF_Y_F;
    float* y_r   = pool + OFF_Y_R;
    float* yp_f  = pool + OFF_YP_F;
    float* yp_r  = pool + OFF_YP_R;
    float* ym_f  = pool + OFF_YM_F;
    float* ym_r  = pool + OFF_YM_R;
    float* sfi   = pool + OFF_SFI;
    float* sif   = pool + OFF_SIF;
    float* xz_cf = pool + OFF_XZ_CF;
    float* xz_cr = pool + OFF_XZ_CR;
    float* xs_cf = pool + OFF_XS_CF;
    float* xs_cr = pool + OFF_XS_CR;
    float* xd_cf = pool + OFF_XD_CF;
    float* xd_cr = pool + OFF_XD_CR;
    float* dt_cf = pool + OFF_DT_CF;
    float* dt_cr = pool + OFF_DT_CR;
    float* y_cf  = pool + OFF_Y_CF;
    float* y_cr  = pool + OFF_Y_CR;
    float* vbuf  = pool + OFF_V;
    float* obuf  = pool + OFF_O;

    const int T1 = 2048, T2 = 2049;

    auto gemm = [&](const float* A, const float* B, const float* bias, float* C,
                    int M, int N, int K, int lda, int ldb, int ldc, int arev, int act) {
        dim3 grid((N + 127) / 128, (M + 127) / 128);
        gemm_kernel<<<grid, 256>>>(A, B, bias, C, M, N, K, lda, ldb, ldc, arev, act);
    };

    // ---- feature extractor: f = relu(x @ feat_w + feat_b)
    gemm(x, feat_w, feat_b, f, T1, 512, 1024, 1024, 512, 512, 0, 1);

    // ---- simple mamba (fwd + rev)
    gemm(f, m_in_w, nullptr, xz_f, T1, 1024, 512, 512, 1024, 1024, 0, 0);
    gemm(f, m_in_w, nullptr, xz_r, T1, 1024, 512, 512, 1024, 1024, 1, 0);

    int nconv = (T1 * DM + 255) / 256;
    conv_silu_kernel<<<nconv, 256>>>(xz_f, m_conv_w, m_conv_b, xs_f, T1);
    conv_silu_kernel<<<nconv, 256>>>(xz_r, m_conv_w, m_conv_b, xs_r, T1);

    gemm(xs_f, m_xproj, nullptr, xd_f, T1, XDW, 512, 512, XDW, XDW, 0, 0);
    gemm(xs_r, m_xproj, nullptr, xd_r, T1, XDW, 512, 512, XDW, XDW, 0, 0);

    gemm(xd_f, m_dt_w, m_dt_b, dt_f, T1, 512, RK, XDW, 512, 512, 0, 2);
    gemm(xd_r, m_dt_w, m_dt_b, dt_r, T1, 512, RK, XDW, 512, 512, 0, 2);

    scan_kernel<<<dim3(64, 2), 256>>>(dt_f, xs_f, xd_f, y_f,
                                      dt_r, xs_r, xd_r, y_r, m_A_log, T1);

    epi_kernel<<<nconv, 256>>>(y_f, xs_f, xz_f, m_D, yp_f, T1);
    epi_kernel<<<nconv, 256>>>(y_r, xs_r, xz_r, m_D, yp_r, T1);

    gemm(yp_f, m_out_w, nullptr, ym_f, T1, 512, 512, 512, 512, 512, 0, 0);
    gemm(yp_r, m_out_w, nullptr, ym_r, T1, 512, 512, 512, 512, 512, 0, 0);

    softmax512_kernel<<<T1, 128>>>(ym_f);
    softmax512_kernel<<<T1, 128>>>(ym_r);

    build_seq_kernel<<<(T2 * 1024 + 255) / 256, 256>>>(ym_f, ym_r, cls1, cls2, sfi, sif);

    // ---- cross mamba (two sequences)
    gemm(sfi, c_in_w, nullptr, xz_cf, T2, 1024, 1024, 1024, 1024, 1024, 0, 0);
    gemm(sif, c_in_w, nullptr, xz_cr, T2, 1024, 1024, 1024, 1024, 1024, 0, 0);

    int nconv2 = (T2 * DM + 255) / 256;
    conv_silu_kernel<<<nconv2, 256>>>(xz_cf, c_conv_w, c_conv_b, xs_cf, T2);
    conv_silu_kernel<<<nconv2, 256>>>(xz_cr, c_conv_w, c_conv_b, xs_cr, T2);

    gemm(xs_cf, c_xproj, nullptr, xd_cf, T2, XDW, 512, 512, XDW, XDW, 0, 0);
    gemm(xs_cr, c_xproj, nullptr, xd_cr, T2, XDW, 512, 512, XDW, XDW, 0, 0);

    gemm(xd_cf, c_dt_w, c_dt_b, dt_cf, T2, 512, RK, XDW, 512, 512, 0, 2);
    gemm(xd_cr, c_dt_w, c_dt_b, dt_cr, T2, 512, RK, XDW, 512, 512, 0, 2);

    scan_kernel<<<dim3(64, 2), 256>>>(dt_cf, xs_cf, xd_cf, y_cf,
                                      dt_cr, xs_cr, xd_cr, y_cr, c_A_log, T2);

    lastrow_epi_kernel<<<2, 512>>>(y_cf, xs_cf, xz_cf, y_cr, xs_cr, xz_cr, c_D, vbuf, T2);
    matvec_outw_kernel<<<dim3(2, 2), 256>>>(vbuf, c_out_w, obuf);
    final_kernel<<<1, 256>>>(obuf, cls_w, cls_b, (float*)d_out);
}

// round 2
// speedup vs baseline: 1.2142x; 1.2142x over previous
#include <cuda_runtime.h>
#include <cstdint>
#include <cstddef>

#define DM 512      // D_INNER / D_MODEL
#define NS 128      // N_STATE
#define RK 32       // DT_RANK
#define XDW 288     // DT_RANK + 2*N_STATE

// ---------------------------------------------------------------------------
// Static scratch pool (no cudaMalloc allowed)
// ---------------------------------------------------------------------------
__device__ float g_pool[33000000];

// offsets (floats)
static const size_t OFF_F     = 0;                      // 2048*512
static const size_t OFF_XZ_F  = 1048576;                // 2048*1024
static const size_t OFF_XZ_R  = 3145728;
static const size_t OFF_XS_F  = 5242880;                // 2048*512
static const size_t OFF_XS_R  = 6291456;
static const size_t OFF_XD_F  = 7340032;                // 2048*288
static const size_t OFF_XD_R  = 7929856;
static const size_t OFF_DT_F  = 8519680;                // 2048*512
static const size_t OFF_DT_R  = 9568256;
static const size_t OFF_Y_F   = 10616832;               // 2048*512
static const size_t OFF_Y_R   = 11665408;
static const size_t OFF_YP_F  = 12713984;               // 2048*512
static const size_t OFF_YP_R  = 13762560;
static const size_t OFF_YM_F  = 14811136;               // 2048*512 (softmaxed in place)
static const size_t OFF_YM_R  = 15859712;
static const size_t OFF_SFI   = 16908288;               // 2049*1024
static const size_t OFF_SIF   = 19006464;
static const size_t OFF_XZ_CF = 21104640;               // 2049*1024
static const size_t OFF_XZ_CR = 23202816;
static const size_t OFF_XS_CF = 25300992;               // 2049*512
static const size_t OFF_XS_CR = 26350080;
static const size_t OFF_XD_CF = 27399168;               // 2049*288
static const size_t OFF_XD_CR = 27989280;
static const size_t OFF_DT_CF = 28579392;               // 2049*512
static const size_t OFF_DT_CR = 29628480;
static const size_t OFF_Y_CF  = 30677568;               // 2049*512
static const size_t OFF_Y_CR  = 31726656;
static const size_t OFF_V     = 32775744;               // 1024 (dir*512+d)
static const size_t OFF_O     = 32776768;               // 1024 (of, oi)

// ---------------------------------------------------------------------------
// Batched GEMM: C[z][M,N] = act( A[z][M,K] @ B[K,N] + bias )
// blockIdx.z selects (A0,C0) or (A1,C1); weights B shared across z.
// arev!=0 => the z==1 A is read with reversed rows.
// 128x128 block tile, BK=16, 256 threads, 8x8 microtile, double-buffered smem.
// act: 0 none, 1 relu, 2 softplus
// ---------------------------------------------------------------------------
__global__ __launch_bounds__(256, 2)
void gemm_kernel(const float* __restrict__ A0, const float* __restrict__ A1,
                 const float* __restrict__ B, const float* __restrict__ bias,
                 float* __restrict__ C0, float* __restrict__ C1,
                 int M, int N, int K, int lda, int ldb, int ldc,
                 int arev, int act)
{
    const float* A = blockIdx.z ? A1 : A0;
    float* C = blockIdx.z ? C1 : C0;
    const int rev = (arev && blockIdx.z) ? 1 : 0;

    __shared__ float As[2][16][128];
    __shared__ float Bs[2][16][128];

    const int tid = threadIdx.x;
    const int bm = blockIdx.y * 128;
    const int bn = blockIdx.x * 128;
    const int tr = (tid >> 4) * 8;
    const int tc = (tid & 15) * 8;

    // loader coords
    const int arow = tid >> 1;            // 0..127
    const int acol = (tid & 1) * 8;       // 0 or 8
    const int brow = tid >> 4;            // 0..15
    const int bcol = (tid & 15) * 8;      // 0..120

    float acc[8][8];
#pragma unroll
    for (int i = 0; i < 8; i++)
#pragma unroll
        for (int j = 0; j < 8; j++) acc[i][j] = 0.f;

    const int ntiles = K >> 4;   // K divisible by 16 for all our launches

    auto loadA = [&](int k0, float4& va0, float4& va1) {
        va0 = make_float4(0.f, 0.f, 0.f, 0.f);
        va1 = va0;
        int m = bm + arow;
        if (m < M) {
            int mm = rev ? (M - 1 - m) : m;
            const float* p = A + (size_t)mm * lda + k0 + acol;
            va0 = *reinterpret_cast<const float4*>(p);
            va1 = *reinterpret_cast<const float4*>(p + 4);
        }
    };
    auto loadB = [&](int k0, float4& vb0, float4& vb1) {
        vb0 = make_float4(0.f, 0.f, 0.f, 0.f);
        vb1 = vb0;
        const float* Brow = B + (size_t)(k0 + brow) * ldb;
        int n0 = bn + bcol;
        if (n0 + 3 < N) vb0 = *reinterpret_cast<const float4*>(Brow + n0);
        else if (n0 < N) {
            vb0.x = Brow[n0];
            if (n0 + 1 < N) vb0.y = Brow[n0 + 1];
            if (n0 + 2 < N) vb0.z = Brow[n0 + 2];
        }
        int n1 = n0 + 4;
        if (n1 + 3 < N) vb1 = *reinterpret_cast<const float4*>(Brow + n1);
        else if (n1 < N) {
            vb1.x = Brow[n1];
            if (n1 + 1 < N) vb1.y = Brow[n1 + 1];
            if (n1 + 2 < N) vb1.z = Brow[n1 + 2];
        }
    };
    auto stageA = [&](int buf, const float4& va0, const float4& va1) {
        As[buf][acol + 0][arow] = va0.x;
        As[buf][acol + 1][arow] = va0.y;
        As[buf][acol + 2][arow] = va0.z;
        As[buf][acol + 3][arow] = va0.w;
        As[buf][acol + 4][arow] = va1.x;
        As[buf][acol + 5][arow] = va1.y;
        As[buf][acol + 6][arow] = va1.z;
        As[buf][acol + 7][arow] = va1.w;
    };
    auto stageB = [&](int buf, const float4& vb0, const float4& vb1) {
        *reinterpret_cast<float4*>(&Bs[buf][brow][bcol])     = vb0;
        *reinterpret_cast<float4*>(&Bs[buf][brow][bcol + 4]) = vb1;
    };

    // prologue: tile 0 -> smem[0]
    {
        float4 va0, va1, vb0, vb1;
        loadA(0, va0, va1);
        loadB(0, vb0, vb1);
        stageA(0, va0, va1);
        stageB(0, vb0, vb1);
    }
    __syncthreads();

    int buf = 0;
    for (int it = 0; it < ntiles; it++) {
        float4 va0, va1, vb0, vb1;
        bool more = (it + 1 < ntiles);
        if (more) {
            loadA((it + 1) << 4, va0, va1);
            loadB((it + 1) << 4, vb0, vb1);
        }
#pragma unroll
        for (int kk = 0; kk < 16; kk++) {
            float a[8], b[8];
            *reinterpret_cast<float4*>(&a[0]) = *reinterpret_cast<const float4*>(&As[buf][kk][tr]);
            *reinterpret_cast<float4*>(&a[4]) = *reinterpret_cast<const float4*>(&As[buf][kk][tr + 4]);
            *reinterpret_cast<float4*>(&b[0]) = *reinterpret_cast<const float4*>(&Bs[buf][kk][tc]);
            *reinterpret_cast<float4*>(&b[4]) = *reinterpret_cast<const float4*>(&Bs[buf][kk][tc + 4]);
#pragma unroll
            for (int i = 0; i < 8; i++)
#pragma unroll
                for (int j = 0; j < 8; j++) acc[i][j] = fmaf(a[i], b[j], acc[i][j]);
        }
        if (more) {
            stageA(buf ^ 1, va0, va1);
            stageB(buf ^ 1, vb0, vb1);
            __syncthreads();
            buf ^= 1;
        }
    }

#pragma unroll
    for (int i = 0; i < 8; i++) {
        int m = bm + tr + i;
        if (m >= M) continue;
#pragma unroll
        for (int j = 0; j < 8; j++) {
            int n = bn + tc + j;
            if (n >= N) continue;
            float v = acc[i][j];
            if (bias) v += bias[n];
            if (act == 1) v = v > 0.f ? v : 0.f;
            else if (act == 2) v = (v > 20.f) ? v : log1pf(__expf(v));
            C[(size_t)m * ldc + n] = v;
        }
    }
}

// ---------------------------------------------------------------------------
// Causal depthwise conv1d (K=4) + SiLU. xz rows are 1024 wide; x = cols [0,512)
// ---------------------------------------------------------------------------
__global__ void conv_silu_kernel(const float* __restrict__ xz0, const float* __restrict__ xz1,
                                 const float* __restrict__ w, const float* __restrict__ b,
                                 float* __restrict__ xs0, float* __restrict__ xs1, int T)
{
    const float* xz = blockIdx.y ? xz1 : xz0;
    float* xs = blockIdx.y ? xs1 : xs0;
    int idx = blockIdx.x * blockDim.x + threadIdx.x;
    if (idx >= T * DM) return;
    int t = idx >> 9;
    int d = idx & 511;
    float acc = b[d];
#pragma unroll
    for (int k = 0; k < 4; k++) {
        int tt = t + k - 3;
        if (tt >= 0) acc = fmaf(xz[(size_t)tt * 1024 + d], w[d * 4 + k], acc);
    }
    xs[idx] = acc / (1.f + __expf(-acc));
}

// ---------------------------------------------------------------------------
// Selective scan with register prefetch. One warp per channel d; lane holds 4
// of the 128 states. 128-thread blocks (4 warps), blockIdx.y = direction.
// ---------------------------------------------------------------------------
__global__ void scan_kernel(const float* __restrict__ dt0, const float* __restrict__ xs0,
                            const float* __restrict__ xd0, float* __restrict__ y0,
                            const float* __restrict__ dt1, const float* __restrict__ xs1,
                            const float* __restrict__ xd1, float* __restrict__ y1,
                            const float* __restrict__ A_log, int T)
{
    const float* dt = blockIdx.y ? dt1 : dt0;
    const float* xs = blockIdx.y ? xs1 : xs0;
    const float* xd = blockIdx.y ? xd1 : xd0;
    float* y = blockIdx.y ? y1 : y0;

    int warp = threadIdx.x >> 5;
    int lane = threadIdx.x & 31;
    int d = blockIdx.x * 4 + warp;

    float4 alv = *reinterpret_cast<const float4*>(A_log + (size_t)d * NS + lane * 4);
    float a0 = -__expf(alv.x), a1 = -__expf(alv.y), a2 = -__expf(alv.z), a3 = -__expf(alv.w);
    float h0 = 0.f, h1 = 0.f, h2 = 0.f, h3 = 0.f;

    const float* pdt = dt + d;
    const float* pxs = xs + d;
    const float* pb = xd + RK + lane * 4;
    const float* pc = pb + NS;

    // prefetch t=0
    float dtv = pdt[0];
    float xv  = pxs[0];
    float4 Bv = *reinterpret_cast<const float4*>(pb);
    float4 Cv = *reinterpret_cast<const float4*>(pc);

    for (int t = 0; t < T - 1; t++) {
        // issue next-iteration loads first (overlap with compute below)
        float dtn = pdt[(size_t)(t + 1) * DM];
        float xn  = pxs[(size_t)(t + 1) * DM];
        float4 Bn = *reinterpret_cast<const float4*>(pb + (size_t)(t + 1) * XDW);
        float4 Cn = *reinterpret_cast<const float4*>(pc + (size_t)(t + 1) * XDW);

        float dtx = dtv * xv;
        h0 = fmaf(h0, __expf(dtv * a0), dtx * Bv.x);
        h1 = fmaf(h1, __expf(dtv * a1), dtx * Bv.y);
        h2 = fmaf(h2, __expf(dtv * a2), dtx * Bv.z);
        h3 = fmaf(h3, __expf(dtv * a3), dtx * Bv.w);
        float acc = h0 * Cv.x + h1 * Cv.y + h2 * Cv.z + h3 * Cv.w;
        acc += __shfl_xor_sync(0xffffffffu, acc, 16);
        acc += __shfl_xor_sync(0xffffffffu, acc, 8);
        acc += __shfl_xor_sync(0xffffffffu, acc, 4);
        acc += __shfl_xor_sync(0xffffffffu, acc, 2);
        acc += __shfl_xor_sync(0xffffffffu, acc, 1);
        if (lane == 0) y[(size_t)t * DM + d] = acc;

        dtv = dtn; xv = xn; Bv = Bn; Cv = Cn;
    }
    // final step t = T-1
    {
        int t = T - 1;
        float dtx = dtv * xv;
        h0 = fmaf(h0, __expf(dtv * a0), dtx * Bv.x);
        h1 = fmaf(h1, __expf(dtv * a1), dtx * Bv.y);
        h2 = fmaf(h2, __expf(dtv * a2), dtx * Bv.z);
        h3 = fmaf(h3, __expf(dtv * a3), dtx * Bv.w);
        float acc = h0 * Cv.x + h1 * Cv.y + h2 * Cv.z + h3 * Cv.w;
        acc += __shfl_xor_sync(0xffffffffu, acc, 16);
        acc += __shfl_xor_sync(0xffffffffu, acc, 8);
        acc += __shfl_xor_sync(0xffffffffu, acc, 4);
        acc += __shfl_xor_sync(0xffffffffu, acc, 2);
        acc += __shfl_xor_sync(0xffffffffu, acc, 1);
        if (lane == 0) y[(size_t)t * DM + d] = acc;
    }
}

// ---------------------------------------------------------------------------
// y = (scan_y + xs*Dp) * silu(z), z = xz[:, 512:1024]; blockIdx.y = direction
// ---------------------------------------------------------------------------
__global__ void epi_kernel(const float* __restrict__ y0, const float* __restrict__ xs0,
                           const float* __restrict__ xz0, float* __restrict__ out0,
                           const float* __restrict__ y1, const float* __restrict__ xs1,
                           const float* __restrict__ xz1, float* __restrict__ out1,
                           const float* __restrict__ Dp, int T)
{
    const float* y  = blockIdx.y ? y1 : y0;
    const float* xs = blockIdx.y ? xs1 : xs0;
    const float* xz = blockIdx.y ? xz1 : xz0;
    float* out = blockIdx.y ? out1 : out0;
    int idx = blockIdx.x * blockDim.x + threadIdx.x;
    if (idx >= T * DM) return;
    int t = idx >> 9, d = idx & 511;
    float v = fmaf(xs[idx], Dp[d], y[idx]);
    float z = xz[(size_t)t * 1024 + 512 + d];
    out[idx] = v * (z / (1.f + __expf(-z)));
}

// ---------------------------------------------------------------------------
// Row-wise softmax over 512 columns, in place. 128 threads per row.
// blockIdx.y = which buffer.
// ---------------------------------------------------------------------------
__global__ void softmax512_kernel(float* __restrict__ d0, float* __restrict__ d1)
{
    float* data = blockIdx.y ? d1 : d0;
    int row = blockIdx.x;
    float* p = data + (size_t)row * DM;
    int tid = threadIdx.x;
    float v[4];
    float mx = -1e30f;
#pragma unroll
    for (int j = 0; j < 4; j++) { v[j] = p[tid + 128 * j]; mx = fmaxf(mx, v[j]); }
#pragma unroll
    for (int o = 16; o; o >>= 1) mx = fmaxf(mx, __shfl_xor_sync(0xffffffffu, mx, o));
    __shared__ float red[4];
    if ((tid & 31) == 0) red[tid >> 5] = mx;
    __syncthreads();
    mx = fmaxf(fmaxf(red[0], red[1]), fmaxf(red[2], red[3]));
    float s = 0.f;
#pragma unroll
    for (int j = 0; j < 4; j++) { v[j] = __expf(v[j] - mx); s += v[j]; }
#pragma unroll
    for (int o = 16; o; o >>= 1) s += __shfl_xor_sync(0xffffffffu, s, o);
    __shared__ float red2[4];
    if ((tid & 31) == 0) red2[tid >> 5] = s;
    __syncthreads();
    s = red2[0] + red2[1] + red2[2] + red2[3];
    float inv = 1.f / s;
#pragma unroll
    for (int j = 0; j < 4; j++) p[tid + 128 * j] = v[j] * inv;
}

// ---------------------------------------------------------------------------
// Build cross-scan sequences
// ---------------------------------------------------------------------------
__global__ void build_seq_kernel(const float* __restrict__ yf, const float* __restrict__ yr,
                                 const float* __restrict__ cls1, const float* __restrict__ cls2,
                                 float* __restrict__ sfi, float* __restrict__ sif)
{
    int idx = blockIdx.x * blockDim.x + threadIdx.x;
    if (idx >= 2049 * 1024) return;
    int t = idx >> 10, j = idx & 1023;
    float vfi, vif;
    if (t < 2048) {
        int jj = (j < 512) ? j : (j - 512);
        float yi = yr[(size_t)(2047 - t) * DM + jj];
        float yfv = yf[(size_t)t * DM + jj];
        vfi = (j < 512) ? yfv : yi;
        vif = (j < 512) ? yi : yfv;
    } else {
        vfi = cls1[j];
        vif = cls2[j];
    }
    sfi[idx] = vfi;
    sif[idx] = vif;
}

// ---------------------------------------------------------------------------
// Cross-mamba last-row epilogue
// ---------------------------------------------------------------------------
__global__ void lastrow_epi_kernel(const float* __restrict__ y0, const float* __restrict__ xs0,
                                   const float* __restrict__ xz0,
                                   const float* __restrict__ y1, const float* __restrict__ xs1,
                                   const float* __restrict__ xz1,
                                   const float* __restrict__ Dp, float* __restrict__ v, int T)
{
    int dir = blockIdx.x;
    const float* y  = dir ? y1 : y0;
    const float* xs = dir ? xs1 : xs0;
    const float* xz = dir ? xz1 : xz0;
    int d = threadIdx.x;
    size_t r = (size_t)(T - 1);
    float val = fmaf(xs[r * DM + d], Dp[d], y[r * DM + d]);
    float z = xz[r * 1024 + 512 + d];
    v[dir * DM + d] = val * (z / (1.f + __expf(-z)));
}

// ---------------------------------------------------------------------------
// o[dir] = v[dir] @ out_w  (512x512 matvec)
// ---------------------------------------------------------------------------
__global__ void matvec_outw_kernel(const float* __restrict__ v, const float* __restrict__ W,
                                   float* __restrict__ o)
{
    int dir = blockIdx.y;
    int j = blockIdx.x * 256 + threadIdx.x;
    __shared__ float sv[DM];
    for (int i = threadIdx.x; i < DM; i += 256) sv[i] = v[dir * DM + i];
    __syncthreads();
    float s = 0.f;
    for (int dd = 0; dd < DM; dd++) s = fmaf(sv[dd], W[(size_t)dd * DM + j], s);
    o[dir * DM + j] = s;
}

// ---------------------------------------------------------------------------
// out = concat(of, oi) @ cls_w + cls_b  -> [1,2]
// ---------------------------------------------------------------------------
__global__ void final_kernel(const float* __restrict__ o, const float* __restrict__ cls_w,
                             const float* __restrict__ cls_b, float* __restrict__ out)
{
    int tid = threadIdx.x; // 256
    float s0 = 0.f, s1 = 0.f;
    for (int j = tid; j < 512; j += 256) {
        float a = o[j], b = o[512 + j];
        s0 += a * cls_w[j * 2 + 0] + b * cls_w[(512 + j) * 2 + 0];
        s1 += a * cls_w[j * 2 + 1] + b * cls_w[(512 + j) * 2 + 1];
    }
#pragma unroll
    for (int off = 16; off; off >>= 1) {
        s0 += __shfl_xor_sync(0xffffffffu, s0, off);
        s1 += __shfl_xor_sync(0xffffffffu, s1, off);
    }
    __shared__ float r0[8], r1[8];
    if ((tid & 31) == 0) { r0[tid >> 5] = s0; r1[tid >> 5] = s1; }
    __syncthreads();
    if (tid == 0) {
        float t0 = 0.f, t1 = 0.f;
        for (int w = 0; w < 8; w++) { t0 += r0[w]; t1 += r1[w]; }
        out[0] = t0 + cls_b[0];
        out[1] = t1 + cls_b[1];
    }
}

// ---------------------------------------------------------------------------
// Host orchestration
// ---------------------------------------------------------------------------
extern "C" void kernel_launch(void* const* d_in, const int* in_sizes, int n_in,
                              void* d_out, int out_size)
{
    const float* x        = (const float*)d_in[0];
    const float* feat_w   = (const float*)d_in[1];
    const float* feat_b   = (const float*)d_in[2];
    const float* cls1     = (const float*)d_in[3];
    const float* cls2     = (const float*)d_in[4];
    const float* cls_w    = (const float*)d_in[5];
    const float* cls_b    = (const float*)d_in[6];
    const float* m_in_w   = (const float*)d_in[7];
    const float* m_conv_w = (const float*)d_in[8];
    const float* m_conv_b = (const float*)d_in[9];
    const float* m_xproj  = (const float*)d_in[10];
    const float* m_dt_w   = (const float*)d_in[11];
    const float* m_dt_b   = (const float*)d_in[12];
    const float* m_A_log  = (const float*)d_in[13];
    const float* m_D      = (const float*)d_in[14];
    const float* m_out_w  = (const float*)d_in[15];
    const float* c_in_w   = (const float*)d_in[16];
    const float* c_conv_w = (const float*)d_in[17];
    const float* c_conv_b = (const float*)d_in[18];
    const float* c_xproj  = (const float*)d_in[19];
    const float* c_dt_w   = (const float*)d_in[20];
    const float* c_dt_b   = (const float*)d_in[21];
    const float* c_A_log  = (const float*)d_in[22];
    const float* c_D      = (const float*)d_in[23];
    const float* c_out_w  = (const float*)d_in[24];

    float* pool = nullptr;
    cudaGetSymbolAddress((void**)&pool, g_pool);

    float* f     = pool + OFF_F;
    float* xz_f  = pool + OFF_XZ_F;
    float* xz_r  = pool + OFF_XZ_R;
    float* xs_f  = pool + OFF_XS_F;
    float* xs_r  = pool + OFF_XS_R;
    float* xd_f  = pool + OFF_XD_F;
    float* xd_r  = pool + OFF_XD_R;
    float* dt_f  = pool + OFF_DT_F;
    float* dt_r  = pool + OFF_DT_R;
    float* y_f   = pool + OFF_Y_F;
    float* y_r   = pool + OFF_Y_R;
    float* yp_f  = pool + OFF_YP_F;
    float* yp_r  = pool + OFF_YP_R;
    float* ym_f  = pool + OFF_YM_F;
    float* ym_r  = pool + OFF_YM_R;
    float* sfi   = pool + OFF_SFI;
    float* sif   = pool + OFF_SIF;
    float* xz_cf = pool + OFF_XZ_CF;
    float* xz_cr = pool + OFF_XZ_CR;
    float* xs_cf = pool + OFF_XS_CF;
    float* xs_cr = pool + OFF_XS_CR;
    float* xd_cf = pool + OFF_XD_CF;
    float* xd_cr = pool + OFF_XD_CR;
    float* dt_cf = pool + OFF_DT_CF;
    float* dt_cr = pool + OFF_DT_CR;
    float* y_cf  = pool + OFF_Y_CF;
    float* y_cr  = pool + OFF_Y_CR;
    float* vbuf  = pool + OFF_V;
    float* obuf  = pool + OFF_O;

    const int T1 = 2048, T2 = 2049;

    auto gemm2 = [&](const float* A0, const float* A1, const float* B, const float* bias,
                     float* C0, float* C1, int M, int N, int K,
                     int lda, int ldb, int ldc, int arev, int act, int nz) {
        dim3 grid((N + 127) / 128, (M + 127) / 128, nz);
        gemm_kernel<<<grid, 256>>>(A0, A1, B, bias, C0, C1, M, N, K, lda, ldb, ldc, arev, act);
    };

    // ---- feature extractor: f = relu(x @ feat_w + feat_b)
    gemm2(x, x, feat_w, feat_b, f, f, T1, 512, 1024, 1024, 512, 512, 0, 1, 1);

    // ---- simple mamba in-proj (fwd + rev in one launch, shared weights)
    gemm2(f, f, m_in_w, nullptr, xz_f, xz_r, T1, 1024, 512, 512, 1024, 1024, 1, 0, 2);

    int nconv = (T1 * DM + 255) / 256;
    conv_silu_kernel<<<dim3(nconv, 2), 256>>>(xz_f, xz_r, m_conv_w, m_conv_b, xs_f, xs_r, T1);

    gemm2(xs_f, xs_r, m_xproj, nullptr, xd_f, xd_r, T1, XDW, 512, 512, XDW, XDW, 0, 0, 2);
    gemm2(xd_f, xd_r, m_dt_w, m_dt_b, dt_f, dt_r, T1, 512, RK, XDW, 512, 512, 0, 2, 2);

    scan_kernel<<<dim3(128, 2), 128>>>(dt_f, xs_f, xd_f, y_f,
                                       dt_r, xs_r, xd_r, y_r, m_A_log, T1);

    epi_kernel<<<dim3(nconv, 2), 256>>>(y_f, xs_f, xz_f, yp_f,
                                        y_r, xs_r, xz_r, yp_r, m_D, T1);

    gemm2(yp_f, yp_r, m_out_w, nullptr, ym_f, ym_r, T1, 512, 512, 512, 512, 512, 0, 0, 2);

    softmax512_kernel<<<dim3(T1, 2), 128>>>(ym_f, ym_r);

    build_seq_kernel<<<(T2 * 1024 + 255) / 256, 256>>>(ym_f, ym_r, cls1, cls2, sfi, sif);

    // ---- cross mamba (two sequences, shared weights)
    gemm2(sfi, sif, c_in_w, nullptr, xz_cf, xz_cr, T2, 1024, 1024, 1024, 1024, 1024, 0, 0, 2);

    int nconv2 = (T2 * DM + 255) / 256;
    conv_silu_kernel<<<dim3(nconv2, 2), 256>>>(xz_cf, xz_cr, c_conv_w, c_conv_b, xs_cf, xs_cr, T2);

    gemm2(xs_cf, xs_cr, c_xproj, nullptr, xd_cf, xd_cr, T2, XDW, 512, 512, XDW, XDW, 0, 0, 2);
    gemm2(xd_cf, xd_cr, c_dt_w, c_dt_b, dt_cf, dt_cr, T2, 512, RK, XDW, 512, 512, 0, 2, 2);

    scan_kernel<<<dim3(128, 2), 128>>>(dt_cf, xs_cf, xd_cf, y_cf,
                                       dt_cr, xs_cr, xd_cr, y_cr, c_A_log, T2);

    lastrow_epi_kernel<<<2, 512>>>(y_cf, xs_cf, xz_cf, y_cr, xs_cr, xz_cr, c_D, vbuf, T2);
    matvec_outw_kernel<<<dim3(2, 2), 256>>>(vbuf, c_out_w, obuf);
    final_kernel<<<1, 256>>>(obuf, cls_w, cls_b, (float*)d_out);
}

// round 3
// speedup vs baseline: 1.7046x; 1.4039x over previous
#include <cuda_runtime.h>
#include <cstdint>
#include <cstddef>

#define DM 512      // D_INNER / D_MODEL
#define NS 128      // N_STATE
#define RK 32       // DT_RANK
#define XDW 288     // DT_RANK + 2*N_STATE

// ---------------------------------------------------------------------------
// Static scratch pool (no cudaMalloc allowed)
// ---------------------------------------------------------------------------
__device__ float g_pool[33000000];

// offsets (floats)
static const size_t OFF_F     = 0;                      // 2048*512
static const size_t OFF_XZ_F  = 1048576;                // 2048*1024
static const size_t OFF_XZ_R  = 3145728;
static const size_t OFF_XS_F  = 5242880;                // 2048*512
static const size_t OFF_XS_R  = 6291456;
static const size_t OFF_XD_F  = 7340032;                // 2048*288
static const size_t OFF_XD_R  = 7929856;
static const size_t OFF_DT_F  = 8519680;                // 2048*512
static const size_t OFF_DT_R  = 9568256;
static const size_t OFF_Y_F   = 10616832;               // 2048*512
static const size_t OFF_Y_R   = 11665408;
static const size_t OFF_YP_F  = 12713984;               // 2048*512
static const size_t OFF_YP_R  = 13762560;
static const size_t OFF_YM_F  = 14811136;               // 2048*512 (softmaxed in place)
static const size_t OFF_YM_R  = 15859712;
static const size_t OFF_SFI   = 16908288;               // 2049*1024
static const size_t OFF_SIF   = 19006464;
static const size_t OFF_XZ_CF = 21104640;               // 2049*1024
static const size_t OFF_XZ_CR = 23202816;
static const size_t OFF_XS_CF = 25300992;               // 2049*512
static const size_t OFF_XS_CR = 26350080;
static const size_t OFF_XD_CF = 27399168;               // 2049*288
static const size_t OFF_XD_CR = 27989280;
static const size_t OFF_DT_CF = 28579392;               // 2049*512
static const size_t OFF_DT_CR = 29628480;
static const size_t OFF_Y_CF  = 30677568;               // 2049*512
static const size_t OFF_Y_CR  = 31726656;
static const size_t OFF_V     = 32775744;               // 1024 (dir*512+d)
static const size_t OFF_O     = 32776768;               // 1024 (of, oi)

__device__ __forceinline__ uint32_t f2tf32(float f) {
    uint32_t u;
    asm("cvt.rna.tf32.f32 %0, %1;" : "=r"(u) : "f"(f));
    return u;
}

// ---------------------------------------------------------------------------
// Tensor-core GEMM (tf32 mma.sync): C[z][M,N] = act( A[z][M,K] @ B[K,N] + bias )
// blockIdx.z selects (A0,C0) or (A1,C1); weights B shared across z.
// arev!=0 => the z==1 A is read with reversed rows.
// 128x128 block tile, BK=16, 256 threads (8 warps, 2x4 -> 64x32 warp tiles).
// Smem padded to stride 136 -> conflict-free fragment loads.
// act: 0 none, 1 relu, 2 softplus
// ---------------------------------------------------------------------------
#define SSTR 136

__global__ __launch_bounds__(256, 2)
void gemm_kernel(const float* __restrict__ A0, const float* __restrict__ A1,
                 const float* __restrict__ B, const float* __restrict__ bias,
                 float* __restrict__ C0, float* __restrict__ C1,
                 int M, int N, int K, int lda, int ldb, int ldc,
                 int arev, int act)
{
    const float* A = blockIdx.z ? A1 : A0;
    float* C = blockIdx.z ? C1 : C0;
    const int rev = (arev && blockIdx.z) ? 1 : 0;

    __shared__ uint32_t As[2][16][SSTR];
    __shared__ uint32_t Bs[2][16][SSTR];

    const int tid = threadIdx.x;
    const int warp = tid >> 5;
    const int lane = tid & 31;
    const int gid = lane >> 2;     // 0..7
    const int tig = lane & 3;      // 0..3
    const int wm = warp >> 2;      // 0..1
    const int wn = warp & 3;       // 0..3

    const int bm = blockIdx.y * 128;
    const int bn = blockIdx.x * 128;

    // loader coords
    const int arow = tid >> 1;            // 0..127
    const int acol = (tid & 1) * 8;       // 0 or 8
    const int brow = tid >> 4;            // 0..15
    const int bcol = (tid & 15) * 8;      // 0..120

    float c[4][4][4];
#pragma unroll
    for (int mi = 0; mi < 4; mi++)
#pragma unroll
        for (int ni = 0; ni < 4; ni++)
#pragma unroll
            for (int r = 0; r < 4; r++) c[mi][ni][r] = 0.f;

    const int ntiles = K >> 4;

    auto loadA = [&](int k0, float4& va0, float4& va1) {
        va0 = make_float4(0.f, 0.f, 0.f, 0.f);
        va1 = va0;
        int m = bm + arow;
        if (m < M) {
            int mm = rev ? (M - 1 - m) : m;
            const float* p = A + (size_t)mm * lda + k0 + acol;
            va0 = *reinterpret_cast<const float4*>(p);
            va1 = *reinterpret_cast<const float4*>(p + 4);
        }
    };
    auto loadB = [&](int k0, float4& vb0, float4& vb1) {
        vb0 = make_float4(0.f, 0.f, 0.f, 0.f);
        vb1 = vb0;
        const float* Brow = B + (size_t)(k0 + brow) * ldb;
        int n0 = bn + bcol;
        if (n0 + 3 < N) vb0 = *reinterpret_cast<const float4*>(Brow + n0);
        else if (n0 < N) {
            vb0.x = Brow[n0];
            if (n0 + 1 < N) vb0.y = Brow[n0 + 1];
            if (n0 + 2 < N) vb0.z = Brow[n0 + 2];
        }
        int n1 = n0 + 4;
        if (n1 + 3 < N) vb1 = *reinterpret_cast<const float4*>(Brow + n1);
        else if (n1 < N) {
            vb1.x = Brow[n1];
            if (n1 + 1 < N) vb1.y = Brow[n1 + 1];
            if (n1 + 2 < N) vb1.z = Brow[n1 + 2];
        }
    };
    auto stageA = [&](int buf, const float4& va0, const float4& va1) {
        As[buf][acol + 0][arow] = f2tf32(va0.x);
        As[buf][acol + 1][arow] = f2tf32(va0.y);
        As[buf][acol + 2][arow] = f2tf32(va0.z);
        As[buf][acol + 3][arow] = f2tf32(va0.w);
        As[buf][acol + 4][arow] = f2tf32(va1.x);
        As[buf][acol + 5][arow] = f2tf32(va1.y);
        As[buf][acol + 6][arow] = f2tf32(va1.z);
        As[buf][acol + 7][arow] = f2tf32(va1.w);
    };
    auto stageB = [&](int buf, const float4& vb0, const float4& vb1) {
        Bs[buf][brow][bcol + 0] = f2tf32(vb0.x);
        Bs[buf][brow][bcol + 1] = f2tf32(vb0.y);
        Bs[buf][brow][bcol + 2] = f2tf32(vb0.z);
        Bs[buf][brow][bcol + 3] = f2tf32(vb0.w);
        Bs[buf][brow][bcol + 4] = f2tf32(vb1.x);
        Bs[buf][brow][bcol + 5] = f2tf32(vb1.y);
        Bs[buf][brow][bcol + 6] = f2tf32(vb1.z);
        Bs[buf][brow][bcol + 7] = f2tf32(vb1.w);
    };

    {
        float4 va0, va1, vb0, vb1;
        loadA(0, va0, va1);
        loadB(0, vb0, vb1);
        stageA(0, va0, va1);
        stageB(0, vb0, vb1);
    }
    __syncthreads();

    int buf = 0;
    for (int it = 0; it < ntiles; it++) {
        float4 va0, va1, vb0, vb1;
        bool more = (it + 1 < ntiles);
        if (more) {
            loadA((it + 1) << 4, va0, va1);
            loadB((it + 1) << 4, vb0, vb1);
        }
#pragma unroll
        for (int k8 = 0; k8 < 16; k8 += 8) {
            uint32_t af[4][4];
            uint32_t bf[4][2];
#pragma unroll
            for (int mi = 0; mi < 4; mi++) {
                int mrow = wm * 64 + mi * 16 + gid;
                af[mi][0] = As[buf][k8 + tig][mrow];
                af[mi][1] = As[buf][k8 + tig][mrow + 8];
                af[mi][2] = As[buf][k8 + tig + 4][mrow];
                af[mi][3] = As[buf][k8 + tig + 4][mrow + 8];
            }
#pragma unroll
            for (int ni = 0; ni < 4; ni++) {
                int ncol = wn * 32 + ni * 8 + gid;
                bf[ni][0] = Bs[buf][k8 + tig][ncol];
                bf[ni][1] = Bs[buf][k8 + tig + 4][ncol];
            }
#pragma unroll
            for (int mi = 0; mi < 4; mi++)
#pragma unroll
                for (int ni = 0; ni < 4; ni++) {
                    asm volatile(
                        "mma.sync.aligned.m16n8k8.row.col.f32.tf32.tf32.f32 "
                        "{%0,%1,%2,%3}, {%4,%5,%6,%7}, {%8,%9}, {%0,%1,%2,%3};"
                        : "+f"(c[mi][ni][0]), "+f"(c[mi][ni][1]),
                          "+f"(c[mi][ni][2]), "+f"(c[mi][ni][3])
                        : "r"(af[mi][0]), "r"(af[mi][1]), "r"(af[mi][2]), "r"(af[mi][3]),
                          "r"(bf[ni][0]), "r"(bf[ni][1]));
                }
        }
        if (more) {
            stageA(buf ^ 1, va0, va1);
            stageB(buf ^ 1, vb0, vb1);
            __syncthreads();
            buf ^= 1;
        }
    }

    // epilogue
#pragma unroll
    for (int mi = 0; mi < 4; mi++) {
#pragma unroll
        for (int ni = 0; ni < 4; ni++) {
            int n = bn + wn * 32 + ni * 8 + 2 * tig;
            if (n >= N) continue;
            float bv = bias ? bias[n] : 0.f;
            float bv2 = bias ? bias[n + 1] : 0.f;
#pragma unroll
            for (int half = 0; half < 2; half++) {
                int m = bm + wm * 64 + mi * 16 + gid + half * 8;
                if (m >= M) continue;
                float v0 = c[mi][ni][half * 2 + 0] + bv;
                float v1 = c[mi][ni][half * 2 + 1] + bv2;
                if (act == 1) {
                    v0 = v0 > 0.f ? v0 : 0.f;
                    v1 = v1 > 0.f ? v1 : 0.f;
                } else if (act == 2) {
                    v0 = (v0 > 20.f) ? v0 : log1pf(__expf(v0));
                    v1 = (v1 > 20.f) ? v1 : log1pf(__expf(v1));
                }
                float2 vv = make_float2(v0, v1);
                *reinterpret_cast<float2*>(C + (size_t)m * ldc + n) = vv;
            }
        }
    }
}

// ---------------------------------------------------------------------------
// Causal depthwise conv1d (K=4) + SiLU. xz rows are 1024 wide; x = cols [0,512)
// ---------------------------------------------------------------------------
__global__ void conv_silu_kernel(const float* __restrict__ xz0, const float* __restrict__ xz1,
                                 const float* __restrict__ w, const float* __restrict__ b,
                                 float* __restrict__ xs0, float* __restrict__ xs1, int T)
{
    const float* xz = blockIdx.y ? xz1 : xz0;
    float* xs = blockIdx.y ? xs1 : xs0;
    int idx = blockIdx.x * blockDim.x + threadIdx.x;
    if (idx >= T * DM) return;
    int t = idx >> 9;
    int d = idx & 511;
    float acc = b[d];
#pragma unroll
    for (int k = 0; k < 4; k++) {
        int tt = t + k - 3;
        if (tt >= 0) acc = fmaf(xz[(size_t)tt * 1024 + d], w[d * 4 + k], acc);
    }
    xs[idx] = acc / (1.f + __expf(-acc));
}

// ---------------------------------------------------------------------------
// Selective scan with register prefetch. One warp (block) per channel d;
// lane holds 4 of the 128 states. blockIdx.y = direction.
// ---------------------------------------------------------------------------
__global__ void scan_kernel(const float* __restrict__ dt0, const float* __restrict__ xs0,
                            const float* __restrict__ xd0, float* __restrict__ y0,
                            const float* __restrict__ dt1, const float* __restrict__ xs1,
                            const float* __restrict__ xd1, float* __restrict__ y1,
                            const float* __restrict__ A_log, int T)
{
    const float* dt = blockIdx.y ? dt1 : dt0;
    const float* xs = blockIdx.y ? xs1 : xs0;
    const float* xd = blockIdx.y ? xd1 : xd0;
    float* y = blockIdx.y ? y1 : y0;

    int lane = threadIdx.x & 31;
    int d = blockIdx.x;

    float4 alv = *reinterpret_cast<const float4*>(A_log + (size_t)d * NS + lane * 4);
    float a0 = -__expf(alv.x), a1 = -__expf(alv.y), a2 = -__expf(alv.z), a3 = -__expf(alv.w);
    float h0 = 0.f, h1 = 0.f, h2 = 0.f, h3 = 0.f;

    const float* pdt = dt + d;
    const float* pxs = xs + d;
    const float* pb = xd + RK + lane * 4;
    const float* pc = pb + NS;

    float dtv = pdt[0];
    float xv  = pxs[0];
    float4 Bv = *reinterpret_cast<const float4*>(pb);
    float4 Cv = *reinterpret_cast<const float4*>(pc);

    for (int t = 0; t < T - 1; t++) {
        float dtn = pdt[(size_t)(t + 1) * DM];
        float xn  = pxs[(size_t)(t + 1) * DM];
        float4 Bn = *reinterpret_cast<const float4*>(pb + (size_t)(t + 1) * XDW);
        float4 Cn = *reinterpret_cast<const float4*>(pc + (size_t)(t + 1) * XDW);

        float dtx = dtv * xv;
        h0 = fmaf(h0, __expf(dtv * a0), dtx * Bv.x);
        h1 = fmaf(h1, __expf(dtv * a1), dtx * Bv.y);
        h2 = fmaf(h2, __expf(dtv * a2), dtx * Bv.z);
        h3 = fmaf(h3, __expf(dtv * a3), dtx * Bv.w);
        float acc = h0 * Cv.x + h1 * Cv.y + h2 * Cv.z + h3 * Cv.w;
        acc += __shfl_xor_sync(0xffffffffu, acc, 16);
        acc += __shfl_xor_sync(0xffffffffu, acc, 8);
        acc += __shfl_xor_sync(0xffffffffu, acc, 4);
        acc += __shfl_xor_sync(0xffffffffu, acc, 2);
        acc += __shfl_xor_sync(0xffffffffu, acc, 1);
        if (lane == 0) y[(size_t)t * DM + d] = acc;

        dtv = dtn; xv = xn; Bv = Bn; Cv = Cn;
    }
    {
        int t = T - 1;
        float dtx = dtv * xv;
        h0 = fmaf(h0, __expf(dtv * a0), dtx * Bv.x);
        h1 = fmaf(h1, __expf(dtv * a1), dtx * Bv.y);
        h2 = fmaf(h2, __expf(dtv * a2), dtx * Bv.z);
        h3 = fmaf(h3, __expf(dtv * a3), dtx * Bv.w);
        float acc = h0 * Cv.x + h1 * Cv.y + h2 * Cv.z + h3 * Cv.w;
        acc += __shfl_xor_sync(0xffffffffu, acc, 16);
        acc += __shfl_xor_sync(0xffffffffu, acc, 8);
        acc += __shfl_xor_sync(0xffffffffu, acc, 4);
        acc += __shfl_xor_sync(0xffffffffu, acc, 2);
        acc += __shfl_xor_sync(0xffffffffu, acc, 1);
        if (lane == 0) y[(size_t)t * DM + d] = acc;
    }
}

// ---------------------------------------------------------------------------
// y = (scan_y + xs*Dp) * silu(z), z = xz[:, 512:1024]; blockIdx.y = direction
// ---------------------------------------------------------------------------
__global__ void epi_kernel(const float* __restrict__ y0, const float* __restrict__ xs0,
                           const float* __restrict__ xz0, float* __restrict__ out0,
                           const float* __restrict__ y1, const float* __restrict__ xs1,
                           const float* __restrict__ xz1, float* __restrict__ out1,
                           const float* __restrict__ Dp, int T)
{
    const float* y  = blockIdx.y ? y1 : y0;
    const float* xs = blockIdx.y ? xs1 : xs0;
    const float* xz = blockIdx.y ? xz1 : xz0;
    float* out = blockIdx.y ? out1 : out0;
    int idx = blockIdx.x * blockDim.x + threadIdx.x;
    if (idx >= T * DM) return;
    int t = idx >> 9, d = idx & 511;
    float v = fmaf(xs[idx], Dp[d], y[idx]);
    float z = xz[(size_t)t * 1024 + 512 + d];
    out[idx] = v * (z / (1.f + __expf(-z)));
}

// ---------------------------------------------------------------------------
// Row-wise softmax over 512 columns, in place. 128 threads per row.
// ---------------------------------------------------------------------------
__global__ void softmax512_kernel(float* __restrict__ d0, float* __restrict__ d1)
{
    float* data = blockIdx.y ? d1 : d0;
    int row = blockIdx.x;
    float* p = data + (size_t)row * DM;
    int tid = threadIdx.x;
    float v[4];
    float mx = -1e30f;
#pragma unroll
    for (int j = 0; j < 4; j++) { v[j] = p[tid + 128 * j]; mx = fmaxf(mx, v[j]); }
#pragma unroll
    for (int o = 16; o; o >>= 1) mx = fmaxf(mx, __shfl_xor_sync(0xffffffffu, mx, o));
    __shared__ float red[4];
    if ((tid & 31) == 0) red[tid >> 5] = mx;
    __syncthreads();
    mx = fmaxf(fmaxf(red[0], red[1]), fmaxf(red[2], red[3]));
    float s = 0.f;
#pragma unroll
    for (int j = 0; j < 4; j++) { v[j] = __expf(v[j] - mx); s += v[j]; }
#pragma unroll
    for (int o = 16; o; o >>= 1) s += __shfl_xor_sync(0xffffffffu, s, o);
    __shared__ float red2[4];
    if ((tid & 31) == 0) red2[tid >> 5] = s;
    __syncthreads();
    s = red2[0] + red2[1] + red2[2] + red2[3];
    float inv = 1.f / s;
#pragma unroll
    for (int j = 0; j < 4; j++) p[tid + 128 * j] = v[j] * inv;
}

// ---------------------------------------------------------------------------
// Build cross-scan sequences
// ---------------------------------------------------------------------------
__global__ void build_seq_kernel(const float* __restrict__ yf, const float* __restrict__ yr,
                                 const float* __restrict__ cls1, const float* __restrict__ cls2,
                                 float* __restrict__ sfi, float* __restrict__ sif)
{
    int idx = blockIdx.x * blockDim.x + threadIdx.x;
    if (idx >= 2049 * 1024) return;
    int t = idx >> 10, j = idx & 1023;
    float vfi, vif;
    if (t < 2048) {
        int jj = (j < 512) ? j : (j - 512);
        float yi = yr[(size_t)(2047 - t) * DM + jj];
        float yfv = yf[(size_t)t * DM + jj];
        vfi = (j < 512) ? yfv : yi;
        vif = (j < 512) ? yi : yfv;
    } else {
        vfi = cls1[j];
        vif = cls2[j];
    }
    sfi[idx] = vfi;
    sif[idx] = vif;
}

// ---------------------------------------------------------------------------
// Cross-mamba last-row epilogue
// ---------------------------------------------------------------------------
__global__ void lastrow_epi_kernel(const float* __restrict__ y0, const float* __restrict__ xs0,
                                   const float* __restrict__ xz0,
                                   const float* __restrict__ y1, const float* __restrict__ xs1,
                                   const float* __restrict__ xz1,
                                   const float* __restrict__ Dp, float* __restrict__ v, int T)
{
    int dir = blockIdx.x;
    const float* y  = dir ? y1 : y0;
    const float* xs = dir ? xs1 : xs0;
    const float* xz = dir ? xz1 : xz0;
    int d = threadIdx.x;
    size_t r = (size_t)(T - 1);
    float val = fmaf(xs[r * DM + d], Dp[d], y[r * DM + d]);
    float z = xz[r * 1024 + 512 + d];
    v[dir * DM + d] = val * (z / (1.f + __expf(-z)));
}

// ---------------------------------------------------------------------------
// o[dir] = v[dir] @ out_w  (512x512 matvec)
// ---------------------------------------------------------------------------
__global__ void matvec_outw_kernel(const float* __restrict__ v, const float* __restrict__ W,
                                   float* __restrict__ o)
{
    int dir = blockIdx.y;
    int j = blockIdx.x * 256 + threadIdx.x;
    __shared__ float sv[DM];
    for (int i = threadIdx.x; i < DM; i += 256) sv[i] = v[dir * DM + i];
    __syncthreads();
    float s = 0.f;
    for (int dd = 0; dd < DM; dd++) s = fmaf(sv[dd], W[(size_t)dd * DM + j], s);
    o[dir * DM + j] = s;
}

// ---------------------------------------------------------------------------
// out = concat(of, oi) @ cls_w + cls_b  -> [1,2]
// ---------------------------------------------------------------------------
__global__ void final_kernel(const float* __restrict__ o, const float* __restrict__ cls_w,
                             const float* __restrict__ cls_b, float* __restrict__ out)
{
    int tid = threadIdx.x; // 256
    float s0 = 0.f, s1 = 0.f;
    for (int j = tid; j < 512; j += 256) {
        float a = o[j], b = o[512 + j];
        s0 += a * cls_w[j * 2 + 0] + b * cls_w[(512 + j) * 2 + 0];
        s1 += a * cls_w[j * 2 + 1] + b * cls_w[(512 + j) * 2 + 1];
    }
#pragma unroll
    for (int off = 16; off; off >>= 1) {
        s0 += __shfl_xor_sync(0xffffffffu, s0, off);
        s1 += __shfl_xor_sync(0xffffffffu, s1, off);
    }
    __shared__ float r0[8], r1[8];
    if ((tid & 31) == 0) { r0[tid >> 5] = s0; r1[tid >> 5] = s1; }
    __syncthreads();
    if (tid == 0) {
        float t0 = 0.f, t1 = 0.f;
        for (int w = 0; w < 8; w++) { t0 += r0[w]; t1 += r1[w]; }
        out[0] = t0 + cls_b[0];
        out[1] = t1 + cls_b[1];
    }
}

// ---------------------------------------------------------------------------
// Host orchestration
// ---------------------------------------------------------------------------
extern "C" void kernel_launch(void* const* d_in, const int* in_sizes, int n_in,
                              void* d_out, int out_size)
{
    const float* x        = (const float*)d_in[0];
    const float* feat_w   = (const float*)d_in[1];
    const float* feat_b   = (const float*)d_in[2];
    const float* cls1     = (const float*)d_in[3];
    const float* cls2     = (const float*)d_in[4];
    const float* cls_w    = (const float*)d_in[5];
    const float* cls_b    = (const float*)d_in[6];
    const float* m_in_w   = (const float*)d_in[7];
    const float* m_conv_w = (const float*)d_in[8];
    const float* m_conv_b = (const float*)d_in[9];
    const float* m_xproj  = (const float*)d_in[10];
    const float* m_dt_w   = (const float*)d_in[11];
    const float* m_dt_b   = (const float*)d_in[12];
    const float* m_A_log  = (const float*)d_in[13];
    const float* m_D      = (const float*)d_in[14];
    const float* m_out_w  = (const float*)d_in[15];
    const float* c_in_w   = (const float*)d_in[16];
    const float* c_conv_w = (const float*)d_in[17];
    const float* c_conv_b = (const float*)d_in[18];
    const float* c_xproj  = (const float*)d_in[19];
    const float* c_dt_w   = (const float*)d_in[20];
    const float* c_dt_b   = (const float*)d_in[21];
    const float* c_A_log  = (const float*)d_in[22];
    const float* c_D      = (const float*)d_in[23];
    const float* c_out_w  = (const float*)d_in[24];

    float* pool = nullptr;
    cudaGetSymbolAddress((void**)&pool, g_pool);

    float* f     = pool + OFF_F;
    float* xz_f  = pool + OFF_XZ_F;
    float* xz_r  = pool + OFF_XZ_R;
    float* xs_f  = pool + OFF_XS_F;
    float* xs_r  = pool + OFF_XS_R;
    float* xd_f  = pool + OFF_XD_F;
    float* xd_r  = pool + OFF_XD_R;
    float* dt_f  = pool + OFF_DT_F;
    float* dt_r  = pool + OFF_DT_R;
    float* y_f   = pool + OFF_Y_F;
    float* y_r   = pool + OFF_Y_R;
    float* yp_f  = pool + OFF_YP_F;
    float* yp_r  = pool + OFF_YP_R;
    float* ym_f  = pool + OFF_YM_F;
    float* ym_r  = pool + OFF_YM_R;
    float* sfi   = pool + OFF_SFI;
    float* sif   = pool + OFF_SIF;
    float* xz_cf = pool + OFF_XZ_CF;
    float* xz_cr = pool + OFF_XZ_CR;
    float* xs_cf = pool + OFF_XS_CF;
    float* xs_cr = pool + OFF_XS_CR;
    float* xd_cf = pool + OFF_XD_CF;
    float* xd_cr = pool + OFF_XD_CR;
    float* dt_cf = pool + OFF_DT_CF;
    float* dt_cr = pool + OFF_DT_CR;
    float* y_cf  = pool + OFF_Y_CF;
    float* y_cr  = pool + OFF_Y_CR;
    float* vbuf  = pool + OFF_V;
    float* obuf  = pool + OFF_O;

    const int T1 = 2048, T2 = 2049;

    auto gemm2 = [&](const float* A0, const float* A1, const float* B, const float* bias,
                     float* C0, float* C1, int M, int N, int K,
                     int lda, int ldb, int ldc, int arev, int act, int nz) {
        dim3 grid((N + 127) / 128, (M + 127) / 128, nz);
        gemm_kernel<<<grid, 256>>>(A0, A1, B, bias, C0, C1, M, N, K, lda, ldb, ldc, arev, act);
    };

    // ---- feature extractor: f = relu(x @ feat_w + feat_b)
    gemm2(x, x, feat_w, feat_b, f, f, T1, 512, 1024, 1024, 512, 512, 0, 1, 1);

    // ---- simple mamba in-proj (fwd + rev in one launch, shared weights)
    gemm2(f, f, m_in_w, nullptr, xz_f, xz_r, T1, 1024, 512, 512, 1024, 1024, 1, 0, 2);

    int nconv = (T1 * DM + 255) / 256;
    conv_silu_kernel<<<dim3(nconv, 2), 256>>>(xz_f, xz_r, m_conv_w, m_conv_b, xs_f, xs_r, T1);

    gemm2(xs_f, xs_r, m_xproj, nullptr, xd_f, xd_r, T1, XDW, 512, 512, XDW, XDW, 0, 0, 2);
    gemm2(xd_f, xd_r, m_dt_w, m_dt_b, dt_f, dt_r, T1, 512, RK, XDW, 512, 512, 0, 2, 2);

    scan_kernel<<<dim3(512, 2), 32>>>(dt_f, xs_f, xd_f, y_f,
                                      dt_r, xs_r, xd_r, y_r, m_A_log, T1);

    epi_kernel<<<dim3(nconv, 2), 256>>>(y_f, xs_f, xz_f, yp_f,
                                        y_r, xs_r, xz_r, yp_r, m_D, T1);

    gemm2(yp_f, yp_r, m_out_w, nullptr, ym_f, ym_r, T1, 512, 512, 512, 512, 512, 0, 0, 2);

    softmax512_kernel<<<dim3(T1, 2), 128>>>(ym_f, ym_r);

    build_seq_kernel<<<(T2 * 1024 + 255) / 256, 256>>>(ym_f, ym_r, cls1, cls2, sfi, sif);

    // ---- cross mamba (two sequences, shared weights)
    gemm2(sfi, sif, c_in_w, nullptr, xz_cf, xz_cr, T2, 1024, 1024, 1024, 1024, 1024, 0, 0, 2);

    int nconv2 = (T2 * DM + 255) / 256;
    conv_silu_kernel<<<dim3(nconv2, 2), 256>>>(xz_cf, xz_cr, c_conv_w, c_conv_b, xs_cf, xs_cr, T2);

    gemm2(xs_cf, xs_cr, c_xproj, nullptr, xd_cf, xd_cr, T2, XDW, 512, 512, XDW, XDW, 0, 0, 2);
    gemm2(xd_cf, xd_cr, c_dt_w, c_dt_b, dt_cf, dt_cr, T2, 512, RK, XDW, 512, 512, 0, 2, 2);

    scan_kernel<<<dim3(512, 2), 32>>>(dt_cf, xs_cf, xd_cf, y_cf,
                                      dt_cr, xs_cr, xd_cr, y_cr, c_A_log, T2);

    lastrow_epi_kernel<<<2, 512>>>(y_cf, xs_cf, xz_cf, y_cr, xs_cr, xz_cr, c_D, vbuf, T2);
    matvec_outw_kernel<<<dim3(2, 2), 256>>>(vbuf, c_out_w, obuf);
    final_kernel<<<1, 256>>>(obuf, cls_w, cls_b, (float*)d_out);
}